// round 8
// baseline (speedup 1.0000x reference)
#include <cuda_runtime.h>
#include <cuda_bf16.h>
#include <cstdint>

#define NN   100000
#define FIN  512
#define HID  256
#define CC   40
#define EE   1600000
#define KIT  10
#define ALPHAF 0.1f

// ---- static device scratch ----
__device__ __align__(128) __nv_bfloat16 g_Xh[(size_t)NN * FIN];
__device__ __align__(128) __nv_bfloat16 g_Xl[(size_t)NN * FIN];
__device__ __align__(128) __nv_bfloat16 g_W1h[FIN * HID];   // [K][N]
__device__ __align__(128) __nv_bfloat16 g_W1l[FIN * HID];
__device__ __align__(128) __nv_bfloat16 g_h1h[(size_t)NN * HID];
__device__ __align__(128) __nv_bfloat16 g_h1l[(size_t)NN * HID];
__device__ __align__(128) __nv_bfloat16 g_W2h[HID * CC];    // [K][N]
__device__ __align__(128) __nv_bfloat16 g_W2l[HID * CC];
__device__ float g_h [NN * CC];
__device__ float g_z0[NN * CC];
__device__ float g_z1[NN * CC];
__device__ float g_dinv[NN];
__device__ int   g_cnt[NN];
__device__ int   g_rowptr[NN + 1];
__device__ int   g_cursor[NN];
__device__ int   g_eidx[EE];
__device__ float g_ew  [EE];

// ===================== helpers =====================
__device__ __forceinline__ uint32_t smem_u32(const void* p) {
    return (uint32_t)__cvta_generic_to_shared(p);
}
__device__ __forceinline__ void ldmatrix_x4(uint32_t* r, uint32_t addr) {
    asm volatile("ldmatrix.sync.aligned.m8n8.x4.shared.b16 {%0,%1,%2,%3}, [%4];"
                 : "=r"(r[0]), "=r"(r[1]), "=r"(r[2]), "=r"(r[3]) : "r"(addr));
}
__device__ __forceinline__ void ldmatrix_x4_trans(uint32_t* r, uint32_t addr) {
    asm volatile("ldmatrix.sync.aligned.m8n8.x4.trans.shared.b16 {%0,%1,%2,%3}, [%4];"
                 : "=r"(r[0]), "=r"(r[1]), "=r"(r[2]), "=r"(r[3]) : "r"(addr));
}
__device__ __forceinline__ void mma_bf16(float* c, const uint32_t* a, const uint32_t* b) {
    asm volatile("mma.sync.aligned.m16n8k16.row.col.f32.bf16.bf16.f32 "
                 "{%0,%1,%2,%3}, {%4,%5,%6,%7}, {%8,%9}, {%0,%1,%2,%3};"
                 : "+f"(c[0]), "+f"(c[1]), "+f"(c[2]), "+f"(c[3])
                 : "r"(a[0]), "r"(a[1]), "r"(a[2]), "r"(a[3]), "r"(b[0]), "r"(b[1]));
}
__device__ __forceinline__ void cp16z(uint32_t dst, const void* src, uint32_t sz) {
    asm volatile("cp.async.cg.shared.global [%0], [%1], 16, %2;"
                 :: "r"(dst), "l"(src), "r"(sz));
}
__device__ __forceinline__ void cp_commit() {
    asm volatile("cp.async.commit_group;");
}
// truncation split: f = hi(bf16 trunc) + lo(bf16 rn)
__device__ __forceinline__ void split4(float4 v, uint2& hi, uint2& lo) {
    uint32_t b0 = __float_as_uint(v.x), b1 = __float_as_uint(v.y);
    uint32_t b2 = __float_as_uint(v.z), b3 = __float_as_uint(v.w);
    float h0 = __uint_as_float(b0 & 0xFFFF0000u);
    float h1 = __uint_as_float(b1 & 0xFFFF0000u);
    float h2 = __uint_as_float(b2 & 0xFFFF0000u);
    float h3 = __uint_as_float(b3 & 0xFFFF0000u);
    hi.x = __byte_perm(b0, b1, 0x7632);
    hi.y = __byte_perm(b2, b3, 0x7632);
    __nv_bfloat162 p0 = __floats2bfloat162_rn(v.x - h0, v.y - h1);
    __nv_bfloat162 p1 = __floats2bfloat162_rn(v.z - h2, v.w - h3);
    lo.x = *reinterpret_cast<uint32_t*>(&p0);
    lo.y = *reinterpret_cast<uint32_t*>(&p1);
}
__device__ __forceinline__ void store_split2(__nv_bfloat16* hibuf, __nv_bfloat16* lobuf,
                                             size_t idx, float x, float y) {
    uint32_t bx = __float_as_uint(x), by = __float_as_uint(y);
    float hx = __uint_as_float(bx & 0xFFFF0000u);
    float hy = __uint_as_float(by & 0xFFFF0000u);
    reinterpret_cast<uint32_t*>(hibuf)[idx >> 1] = __byte_perm(bx, by, 0x7632);
    __nv_bfloat162 lo = __floats2bfloat162_rn(x - hx, y - hy);
    reinterpret_cast<uint32_t*>(lobuf)[idx >> 1] = *reinterpret_cast<uint32_t*>(&lo);
}

// ===================== one-off split kernels =====================
__global__ void split_x(const float* __restrict__ X) {
    size_t i = (size_t)blockIdx.x * blockDim.x + threadIdx.x;
    if (i >= (size_t)NN * FIN / 4) return;
    float4 v = reinterpret_cast<const float4*>(X)[i];
    uint2 hi, lo;
    split4(v, hi, lo);
    reinterpret_cast<uint2*>(g_Xh)[i] = hi;
    reinterpret_cast<uint2*>(g_Xl)[i] = lo;
}
__global__ void split_w1(const float* __restrict__ W1) {
    int i = blockIdx.x * blockDim.x + threadIdx.x;
    if (i >= FIN * HID / 4) return;
    float4 v = reinterpret_cast<const float4*>(W1)[i];
    uint2 hi, lo;
    split4(v, hi, lo);
    reinterpret_cast<uint2*>(g_W1h)[i] = hi;
    reinterpret_cast<uint2*>(g_W1l)[i] = lo;
}
__global__ void split_w2(const float* __restrict__ W2) {
    int i = blockIdx.x * blockDim.x + threadIdx.x;
    if (i >= HID * CC / 4) return;
    float4 v = reinterpret_cast<const float4*>(W2)[i];
    uint2 hi, lo;
    split4(v, hi, lo);
    reinterpret_cast<uint2*>(g_W2h)[i] = hi;
    reinterpret_cast<uint2*>(g_W2l)[i] = lo;
}

// ===================== GEMM1: h1 = relu(X @ W1 + b1) =====================
// double-buffered cp.async, 2 CTAs/SM, merged hi/lo B ldmatrix
#define SA 40
#define SB 136
#define A_BUF (128 * SA * 2)          // 10240 B
#define B_BUF (32 * SB * 2)           // 8704 B
#define ST1   (2 * A_BUF + 2 * B_BUF) // 37888 B per stage
#define G1_SMEM (2 * ST1)             // 75776 B
#define NKT (FIN / 32)                // 16

__global__ __launch_bounds__(256, 2)
void gemm1_tc(const float* __restrict__ bias) {
    extern __shared__ __align__(16) char sm1[];

    const int tid  = threadIdx.x;
    const int lane = tid & 31;
    const int warp = tid >> 5;
    const int wm   = warp >> 2;
    const int wn   = warp & 3;
    const int bm   = blockIdx.y * 128;
    const int bn   = blockIdx.x * 128;

    // cp.async mapping
    const int arow = tid >> 1;
    const int akp  = (tid & 1) * 16;
    const int brow = tid >> 3;
    const int bcol = (tid & 7) * 16;
    const uint32_t xsz = ((bm + arow) < NN) ? 16u : 0u;

    const __nv_bfloat16* srcAh = g_Xh + (size_t)(bm + arow) * FIN + akp;
    const __nv_bfloat16* srcAl = g_Xl + (size_t)(bm + arow) * FIN + akp;
    const __nv_bfloat16* srcBh = g_W1h + (size_t)brow * HID + bn + bcol;
    const __nv_bfloat16* srcBl = g_W1l + (size_t)brow * HID + bn + bcol;

    const uint32_t smb = smem_u32(sm1);
    const uint32_t dAh = smb + arow * (SA * 2) + akp * 2;
    const uint32_t dAl = dAh + A_BUF;
    const uint32_t dBh = smb + 2 * A_BUF + brow * (SB * 2) + bcol * 2;
    const uint32_t dBl = dBh + B_BUF;

    auto load_stage = [&](int kt, int s) {
        const uint32_t so = (uint32_t)s * ST1;
        const int ko = kt * 32;
        cp16z(dAh + so,      srcAh + ko,     xsz);
        cp16z(dAh + so + 16, srcAh + ko + 8, xsz);
        cp16z(dAl + so,      srcAl + ko,     xsz);
        cp16z(dAl + so + 16, srcAl + ko + 8, xsz);
        cp16z(dBh + so,      srcBh + (size_t)ko * HID,     16u);
        cp16z(dBh + so + 16, srcBh + (size_t)ko * HID + 8, 16u);
        cp16z(dBl + so,      srcBl + (size_t)ko * HID,     16u);
        cp16z(dBl + so + 16, srcBl + (size_t)ko * HID + 8, 16u);
        cp_commit();
    };

    float acc[4][4][4];
#pragma unroll
    for (int i = 0; i < 4; i++)
#pragma unroll
        for (int j = 0; j < 4; j++)
#pragma unroll
            for (int k = 0; k < 4; k++) acc[i][j][k] = 0.f;

    const int agrp   = lane >> 3;
    const int arow_l = (agrp & 1) * 8 + (lane & 7);
    const int akcol  = (agrp >> 1) * 8;
    // merged-B ldmatrix: lanes 0-15 read Bh rows, lanes 16-31 read Bl rows
    const int bkrow  = lane & 15;
    const uint32_t bsel = (lane < 16) ? 0u : (uint32_t)B_BUF;

    load_stage(0, 0);

    for (int kt = 0; kt < NKT; kt++) {
        const int s = kt & 1;
        const uint32_t so = (uint32_t)s * ST1;

        if (kt + 1 < NKT) {
            load_stage(kt + 1, s ^ 1);
            asm volatile("cp.async.wait_group 1;");
        } else {
            asm volatile("cp.async.wait_group 0;");
        }
        __syncthreads();

#pragma unroll
        for (int ks = 0; ks < 32; ks += 16) {
            uint32_t a_h[4][4], a_l[4][4];
#pragma unroll
            for (int im = 0; im < 4; im++) {
                int mrow = wm * 64 + im * 16 + arow_l;
                uint32_t abase = smb + so + mrow * (SA * 2) + (ks + akcol) * 2;
                ldmatrix_x4(a_h[im], abase);
                ldmatrix_x4(a_l[im], abase + A_BUF);
            }
#pragma unroll
            for (int in_ = 0; in_ < 4; in_++) {
                int ncol = wn * 32 + in_ * 8;
                uint32_t bb[4];
                uint32_t baddr = smb + so + 2 * A_BUF + bsel
                               + (ks + bkrow) * (SB * 2) + ncol * 2;
                ldmatrix_x4_trans(bb, baddr);   // bb[0..1]=Bh, bb[2..3]=Bl
#pragma unroll
                for (int im = 0; im < 4; im++) {
                    mma_bf16(acc[im][in_], a_h[im], &bb[0]);
                    mma_bf16(acc[im][in_], a_h[im], &bb[2]);
                    mma_bf16(acc[im][in_], a_l[im], &bb[0]);
                }
            }
        }
        __syncthreads();
    }

    // epilogue: bias + relu, write h1 as split bf16
    const int r_in = lane >> 2;
    const int c_in = (lane & 3) * 2;
#pragma unroll
    for (int in_ = 0; in_ < 4; in_++) {
        int col = bn + wn * 32 + in_ * 8 + c_in;
        float b0 = bias[col], b1 = bias[col + 1];
#pragma unroll
        for (int im = 0; im < 4; im++) {
            int row0 = bm + wm * 64 + im * 16 + r_in;
            if (row0 < NN) {
                float ox = fmaxf(acc[im][in_][0] + b0, 0.f);
                float oy = fmaxf(acc[im][in_][1] + b1, 0.f);
                store_split2(g_h1h, g_h1l, (size_t)row0 * HID + col, ox, oy);
            }
            int row1 = row0 + 8;
            if (row1 < NN) {
                float ox = fmaxf(acc[im][in_][2] + b0, 0.f);
                float oy = fmaxf(acc[im][in_][3] + b1, 0.f);
                store_split2(g_h1h, g_h1l, (size_t)row1 * HID + col, ox, oy);
            }
        }
    }
}

// ===================== GEMM2: h = relu(h1 @ W2 + b2) =====================
#define SB2 48
#define SA2 72
#define G2_SMEM ((HID * SB2 * 2 + 128 * SA2 * 2) * 2)

__global__ __launch_bounds__(256, 2)
void gemm2_tc(const float* __restrict__ b2) {
    extern __shared__ __align__(16) char sm2[];
    __nv_bfloat16* W2hs = reinterpret_cast<__nv_bfloat16*>(sm2);
    __nv_bfloat16* W2ls = W2hs + HID * SB2;
    __nv_bfloat16* A2h  = W2ls + HID * SB2;
    __nv_bfloat16* A2l  = A2h + 128 * SA2;

    const int tid  = threadIdx.x;
    const int lane = tid & 31;
    const int warp = tid >> 5;
    const int bm   = blockIdx.x * 128;

    for (int i = tid; i < HID * CC; i += 256) {
        int k = i / CC, n = i % CC;
        W2hs[k * SB2 + n] = g_W2h[i];
        W2ls[k * SB2 + n] = g_W2l[i];
    }

    float acc[5][4];
#pragma unroll
    for (int n = 0; n < 5; n++)
#pragma unroll
        for (int j = 0; j < 4; j++) acc[n][j] = 0.f;

    const int agrp   = lane >> 3;
    const int arow_l = (agrp & 1) * 8 + (lane & 7);
    const int akcol  = (agrp >> 1) * 8;
    const int bkrow  = lane & 15;
    const int bsel   = (lane < 16) ? 0 : HID * SB2;   // Bh vs Bl (elements)

    const int arow  = tid >> 1;
    const int apart = (tid & 1) * 32;
    const bool aok  = (bm + arow) < NN;
    const uint4 zz  = make_uint4(0, 0, 0, 0);

    for (int kc = 0; kc < 4; kc++) {
#pragma unroll
        for (int j = 0; j < 4; j++) {
            size_t gidx = (size_t)(bm + arow) * HID + kc * 64 + apart + j * 8;
            uint4 vh = aok ? *reinterpret_cast<const uint4*>(&g_h1h[gidx]) : zz;
            uint4 vl = aok ? *reinterpret_cast<const uint4*>(&g_h1l[gidx]) : zz;
            *reinterpret_cast<uint4*>(&A2h[arow * SA2 + apart + j * 8]) = vh;
            *reinterpret_cast<uint4*>(&A2l[arow * SA2 + apart + j * 8]) = vl;
        }
        __syncthreads();

#pragma unroll
        for (int ks = 0; ks < 64; ks += 16) {
            uint32_t a_h[4], a_l[4];
            ldmatrix_x4(a_h, smem_u32(&A2h[(warp * 16 + arow_l) * SA2 + ks + akcol]));
            ldmatrix_x4(a_l, smem_u32(&A2l[(warp * 16 + arow_l) * SA2 + ks + akcol]));
#pragma unroll
            for (int n = 0; n < 5; n++) {
                uint32_t bb[4];
                ldmatrix_x4_trans(bb, smem_u32(&W2hs[bsel + (kc * 64 + ks + bkrow) * SB2 + n * 8]));
                mma_bf16(acc[n], a_h, &bb[0]);
                mma_bf16(acc[n], a_h, &bb[2]);
                mma_bf16(acc[n], a_l, &bb[0]);
            }
        }
        __syncthreads();
    }

    const int r_in = lane >> 2;
    const int c_in = (lane & 3) * 2;
    const int row0 = bm + warp * 16 + r_in;
    const int row1 = row0 + 8;
#pragma unroll
    for (int n = 0; n < 5; n++) {
        int col = n * 8 + c_in;
        float bb0 = b2[col], bb1 = b2[col + 1];
        if (row0 < NN) {
            float2 o;
            o.x = fmaxf(acc[n][0] + bb0, 0.f);
            o.y = fmaxf(acc[n][1] + bb1, 0.f);
            *reinterpret_cast<float2*>(&g_h[(size_t)row0 * CC + col]) = o;
        }
        if (row1 < NN) {
            float2 o;
            o.x = fmaxf(acc[n][2] + bb0, 0.f);
            o.y = fmaxf(acc[n][3] + bb1, 0.f);
            *reinterpret_cast<float2*>(&g_h[(size_t)row1 * CC + col]) = o;
        }
    }
}

// ================= degree / CSR build =================
__global__ void zero_cnt() {
    int i = blockIdx.x * blockDim.x + threadIdx.x;
    if (i < NN) g_cnt[i] = 0;
}
__global__ void count_deg(const int* __restrict__ dst) {
    int e = blockIdx.x * blockDim.x + threadIdx.x;
    if (e < EE) atomicAdd(&g_cnt[dst[e]], 1);
}
__global__ void calc_dinv() {
    int i = blockIdx.x * blockDim.x + threadIdx.x;
    if (i < NN) g_dinv[i] = rsqrtf((float)g_cnt[i] + 1.0f);
}
__global__ void scan_rowptr() {
    __shared__ int s[1024];
    __shared__ int carry;
    const int tid = threadIdx.x;
    if (tid == 0) carry = 0;
    __syncthreads();
    for (int base = 0; base < NN; base += 1024) {
        int i = base + tid;
        int v = (i < NN) ? g_cnt[i] : 0;
        s[tid] = v;
        __syncthreads();
#pragma unroll
        for (int off = 1; off < 1024; off <<= 1) {
            int t = (tid >= off) ? s[tid - off] : 0;
            __syncthreads();
            s[tid] += t;
            __syncthreads();
        }
        if (i < NN) {
            int ex = carry + s[tid] - v;
            g_rowptr[i] = ex;
            g_cursor[i] = ex;
        }
        __syncthreads();
        if (tid == 0) carry += s[1023];
        __syncthreads();
    }
    if (tid == 0) g_rowptr[NN] = carry;
}
__global__ void fill_csr(const int* __restrict__ src, const int* __restrict__ dst) {
    int e = blockIdx.x * blockDim.x + threadIdx.x;
    if (e >= EE) return;
    int s = src[e];
    int d = dst[e];
    int pos = atomicAdd(&g_cursor[d], 1);
    g_eidx[pos] = s;
    g_ew[pos]   = g_dinv[s] * g_dinv[d];
}

// ================= fused propagation step =================
__global__ __launch_bounds__(320)
void prop_step(const float* __restrict__ z,
               float* __restrict__ zn) {
    const int tid  = blockIdx.x * blockDim.x + threadIdx.x;
    const int node = tid / 10;
    const int q    = tid % 10;
    if (node >= NN) return;

    const int beg = g_rowptr[node];
    const int end = g_rowptr[node + 1];

    const float4* __restrict__ z4 = reinterpret_cast<const float4*>(z);

    float4 acc = make_float4(0.f, 0.f, 0.f, 0.f);
#pragma unroll 2
    for (int e = beg; e < end; e++) {
        const int   s = __ldg(&g_eidx[e]);
        const float w = __ldg(&g_ew[e]);
        float4 v = __ldg(&z4[(size_t)s * 10 + q]);
        acc.x += w * v.x;
        acc.y += w * v.y;
        acc.z += w * v.z;
        acc.w += w * v.w;
    }

    const float di = g_dinv[node];
    const float sw = di * di;
    const float4 zc = z4[(size_t)node * 10 + q];
    const float4 hh = reinterpret_cast<const float4*>(g_h)[(size_t)node * 10 + q];

    float4 o;
    o.x = (1.0f - ALPHAF) * (acc.x + sw * zc.x) + ALPHAF * hh.x;
    o.y = (1.0f - ALPHAF) * (acc.y + sw * zc.y) + ALPHAF * hh.y;
    o.z = (1.0f - ALPHAF) * (acc.z + sw * zc.z) + ALPHAF * hh.z;
    o.w = (1.0f - ALPHAF) * (acc.w + sw * zc.w) + ALPHAF * hh.w;
    reinterpret_cast<float4*>(zn)[(size_t)node * 10 + q] = o;
}

// ================= launch =================
extern "C" void kernel_launch(void* const* d_in, const int* in_sizes, int n_in,
                              void* d_out, int out_size) {
    const float* x  = (const float*)d_in[0];
    const int*   ei = (const int*)  d_in[1];
    const float* W1 = (const float*)d_in[2];
    const float* b1 = (const float*)d_in[3];
    const float* W2 = (const float*)d_in[4];
    const float* b2 = (const float*)d_in[5];
    float* out = (float*)d_out;

    const int* src = ei;
    const int* dst = ei + EE;

    float *p_h, *p_z0, *p_z1;
    cudaGetSymbolAddress((void**)&p_h,  g_h);
    cudaGetSymbolAddress((void**)&p_z0, g_z0);
    cudaGetSymbolAddress((void**)&p_z1, g_z1);

    // splits
    split_x <<<(int)(((size_t)NN * FIN / 4 + 255) / 256), 256>>>(x);
    split_w1<<<(FIN * HID / 4 + 255) / 256, 256>>>(W1);
    split_w2<<<(HID * CC / 4 + 255) / 256, 256>>>(W2);

    // MLP on tensor cores
    cudaFuncSetAttribute(gemm1_tc, cudaFuncAttributeMaxDynamicSharedMemorySize, G1_SMEM);
    dim3 g1(HID / 128, (NN + 127) / 128);
    gemm1_tc<<<g1, 256, G1_SMEM>>>(b1);
    cudaFuncSetAttribute(gemm2_tc, cudaFuncAttributeMaxDynamicSharedMemorySize, G2_SMEM);
    gemm2_tc<<<(NN + 127) / 128, 256, G2_SMEM>>>(b2);

    // CSR build (by destination)
    zero_cnt <<<(NN + 255) / 256, 256>>>();
    count_deg<<<(EE + 255) / 256, 256>>>(dst);
    calc_dinv<<<(NN + 255) / 256, 256>>>();
    scan_rowptr<<<1, 1024>>>();
    fill_csr <<<(EE + 255) / 256, 256>>>(src, dst);

    // K fused propagation steps (ping-pong)
    const int threads = NN * 10;
    const int blocks  = (threads + 319) / 320;
    for (int it = 0; it < KIT; it++) {
        const float* zcur = (it == 0) ? p_h : ((it & 1) ? p_z1 : p_z0);
        float* znext = (it == KIT - 1) ? out : ((it & 1) ? p_z0 : p_z1);
        prop_step<<<blocks, 320>>>(zcur, znext);
    }
}

// round 9
// speedup vs baseline: 1.0054x; 1.0054x over previous
#include <cuda_runtime.h>
#include <cuda_bf16.h>
#include <cstdint>

#define NN   100000
#define FIN  512
#define HID  256
#define CC   40
#define EE   1600000
#define KIT  10
#define ALPHAF 0.1f

// ---- static device scratch ----
__device__ __align__(128) __nv_bfloat16 g_Xh[(size_t)NN * FIN];
__device__ __align__(128) __nv_bfloat16 g_Xl[(size_t)NN * FIN];
__device__ __align__(128) __nv_bfloat16 g_W1h[FIN * HID];   // [K][N]
__device__ __align__(128) __nv_bfloat16 g_W1l[FIN * HID];
__device__ __align__(128) __nv_bfloat16 g_h1h[(size_t)NN * HID];
__device__ __align__(128) __nv_bfloat16 g_h1l[(size_t)NN * HID];
__device__ __align__(128) __nv_bfloat16 g_W2h[HID * CC];    // [K][N]
__device__ __align__(128) __nv_bfloat16 g_W2l[HID * CC];
__device__ float g_h [NN * CC];
__device__ float g_z0[NN * CC];
__device__ float g_z1[NN * CC];
__device__ float g_dinv[NN];
__device__ int   g_cnt[NN];
__device__ int   g_rowptr[NN + 1];
__device__ int   g_cursor[NN];
__device__ int   g_eidx[EE];
__device__ float g_ew  [EE];

// ===================== helpers =====================
__device__ __forceinline__ uint32_t smem_u32(const void* p) {
    return (uint32_t)__cvta_generic_to_shared(p);
}
__device__ __forceinline__ void ldmatrix_x4(uint32_t* r, uint32_t addr) {
    asm volatile("ldmatrix.sync.aligned.m8n8.x4.shared.b16 {%0,%1,%2,%3}, [%4];"
                 : "=r"(r[0]), "=r"(r[1]), "=r"(r[2]), "=r"(r[3]) : "r"(addr));
}
__device__ __forceinline__ void ldmatrix_x4_trans(uint32_t* r, uint32_t addr) {
    asm volatile("ldmatrix.sync.aligned.m8n8.x4.trans.shared.b16 {%0,%1,%2,%3}, [%4];"
                 : "=r"(r[0]), "=r"(r[1]), "=r"(r[2]), "=r"(r[3]) : "r"(addr));
}
__device__ __forceinline__ void mma_bf16(float* c, const uint32_t* a, const uint32_t* b) {
    asm volatile("mma.sync.aligned.m16n8k16.row.col.f32.bf16.bf16.f32 "
                 "{%0,%1,%2,%3}, {%4,%5,%6,%7}, {%8,%9}, {%0,%1,%2,%3};"
                 : "+f"(c[0]), "+f"(c[1]), "+f"(c[2]), "+f"(c[3])
                 : "r"(a[0]), "r"(a[1]), "r"(a[2]), "r"(a[3]), "r"(b[0]), "r"(b[1]));
}
__device__ __forceinline__ void cp16z(uint32_t dst, const void* src, uint32_t sz) {
    asm volatile("cp.async.cg.shared.global [%0], [%1], 16, %2;"
                 :: "r"(dst), "l"(src), "r"(sz));
}
__device__ __forceinline__ void cp_commit() {
    asm volatile("cp.async.commit_group;");
}
// truncation split: f = hi(bf16 trunc) + lo(bf16 rn)
__device__ __forceinline__ void split4(float4 v, uint2& hi, uint2& lo) {
    uint32_t b0 = __float_as_uint(v.x), b1 = __float_as_uint(v.y);
    uint32_t b2 = __float_as_uint(v.z), b3 = __float_as_uint(v.w);
    float h0 = __uint_as_float(b0 & 0xFFFF0000u);
    float h1 = __uint_as_float(b1 & 0xFFFF0000u);
    float h2 = __uint_as_float(b2 & 0xFFFF0000u);
    float h3 = __uint_as_float(b3 & 0xFFFF0000u);
    hi.x = __byte_perm(b0, b1, 0x7632);
    hi.y = __byte_perm(b2, b3, 0x7632);
    __nv_bfloat162 p0 = __floats2bfloat162_rn(v.x - h0, v.y - h1);
    __nv_bfloat162 p1 = __floats2bfloat162_rn(v.z - h2, v.w - h3);
    lo.x = *reinterpret_cast<uint32_t*>(&p0);
    lo.y = *reinterpret_cast<uint32_t*>(&p1);
}
__device__ __forceinline__ void store_split2(__nv_bfloat16* hibuf, __nv_bfloat16* lobuf,
                                             size_t idx, float x, float y) {
    uint32_t bx = __float_as_uint(x), by = __float_as_uint(y);
    float hx = __uint_as_float(bx & 0xFFFF0000u);
    float hy = __uint_as_float(by & 0xFFFF0000u);
    reinterpret_cast<uint32_t*>(hibuf)[idx >> 1] = __byte_perm(bx, by, 0x7632);
    __nv_bfloat162 lo = __floats2bfloat162_rn(x - hx, y - hy);
    reinterpret_cast<uint32_t*>(lobuf)[idx >> 1] = *reinterpret_cast<uint32_t*>(&lo);
}

// ===================== one-off split kernels =====================
__global__ void split_x(const float* __restrict__ X) {
    size_t i = (size_t)blockIdx.x * blockDim.x + threadIdx.x;
    if (i >= (size_t)NN * FIN / 4) return;
    float4 v = reinterpret_cast<const float4*>(X)[i];
    uint2 hi, lo;
    split4(v, hi, lo);
    reinterpret_cast<uint2*>(g_Xh)[i] = hi;
    reinterpret_cast<uint2*>(g_Xl)[i] = lo;
}
__global__ void split_w1(const float* __restrict__ W1) {
    int i = blockIdx.x * blockDim.x + threadIdx.x;
    if (i >= FIN * HID / 4) return;
    float4 v = reinterpret_cast<const float4*>(W1)[i];
    uint2 hi, lo;
    split4(v, hi, lo);
    reinterpret_cast<uint2*>(g_W1h)[i] = hi;
    reinterpret_cast<uint2*>(g_W1l)[i] = lo;
}
__global__ void split_w2(const float* __restrict__ W2) {
    int i = blockIdx.x * blockDim.x + threadIdx.x;
    if (i >= HID * CC / 4) return;
    float4 v = reinterpret_cast<const float4*>(W2)[i];
    uint2 hi, lo;
    split4(v, hi, lo);
    reinterpret_cast<uint2*>(g_W2h)[i] = hi;
    reinterpret_cast<uint2*>(g_W2l)[i] = lo;
}

// ===================== GEMM1: h1 = relu(X @ W1 + b1) =====================
// double-buffered cp.async, 2 CTAs/SM, merged hi/lo B ldmatrix
#define SA 40
#define SB 136
#define A_BUF (128 * SA * 2)          // 10240 B
#define B_BUF (32 * SB * 2)           // 8704 B
#define ST1   (2 * A_BUF + 2 * B_BUF) // 37888 B per stage
#define G1_SMEM (2 * ST1)             // 75776 B
#define NKT (FIN / 32)                // 16

__global__ __launch_bounds__(256, 2)
void gemm1_tc(const float* __restrict__ bias) {
    extern __shared__ __align__(16) char sm1[];

    const int tid  = threadIdx.x;
    const int lane = tid & 31;
    const int warp = tid >> 5;
    const int wm   = warp >> 2;
    const int wn   = warp & 3;
    const int bm   = blockIdx.y * 128;
    const int bn   = blockIdx.x * 128;

    // cp.async mapping
    const int arow = tid >> 1;
    const int akp  = (tid & 1) * 16;
    const int brow = tid >> 3;
    const int bcol = (tid & 7) * 16;
    const uint32_t xsz = ((bm + arow) < NN) ? 16u : 0u;

    const __nv_bfloat16* srcAh = g_Xh + (size_t)(bm + arow) * FIN + akp;
    const __nv_bfloat16* srcAl = g_Xl + (size_t)(bm + arow) * FIN + akp;
    const __nv_bfloat16* srcBh = g_W1h + (size_t)brow * HID + bn + bcol;
    const __nv_bfloat16* srcBl = g_W1l + (size_t)brow * HID + bn + bcol;

    const uint32_t smb = smem_u32(sm1);
    const uint32_t dAh = smb + arow * (SA * 2) + akp * 2;
    const uint32_t dAl = dAh + A_BUF;
    const uint32_t dBh = smb + 2 * A_BUF + brow * (SB * 2) + bcol * 2;
    const uint32_t dBl = dBh + B_BUF;

    auto load_stage = [&](int kt, int s) {
        const uint32_t so = (uint32_t)s * ST1;
        const int ko = kt * 32;
        cp16z(dAh + so,      srcAh + ko,     xsz);
        cp16z(dAh + so + 16, srcAh + ko + 8, xsz);
        cp16z(dAl + so,      srcAl + ko,     xsz);
        cp16z(dAl + so + 16, srcAl + ko + 8, xsz);
        cp16z(dBh + so,      srcBh + (size_t)ko * HID,     16u);
        cp16z(dBh + so + 16, srcBh + (size_t)ko * HID + 8, 16u);
        cp16z(dBl + so,      srcBl + (size_t)ko * HID,     16u);
        cp16z(dBl + so + 16, srcBl + (size_t)ko * HID + 8, 16u);
        cp_commit();
    };

    float acc[4][4][4];
#pragma unroll
    for (int i = 0; i < 4; i++)
#pragma unroll
        for (int j = 0; j < 4; j++)
#pragma unroll
            for (int k = 0; k < 4; k++) acc[i][j][k] = 0.f;

    const int agrp   = lane >> 3;
    const int arow_l = (agrp & 1) * 8 + (lane & 7);
    const int akcol  = (agrp >> 1) * 8;
    // merged-B ldmatrix: lanes 0-15 read Bh rows, lanes 16-31 read Bl rows
    const int bkrow  = lane & 15;
    const uint32_t bsel = (lane < 16) ? 0u : (uint32_t)B_BUF;

    load_stage(0, 0);

    for (int kt = 0; kt < NKT; kt++) {
        const int s = kt & 1;
        const uint32_t so = (uint32_t)s * ST1;

        if (kt + 1 < NKT) {
            load_stage(kt + 1, s ^ 1);
            asm volatile("cp.async.wait_group 1;");
        } else {
            asm volatile("cp.async.wait_group 0;");
        }
        __syncthreads();

#pragma unroll
        for (int ks = 0; ks < 32; ks += 16) {
            uint32_t a_h[4][4], a_l[4][4];
#pragma unroll
            for (int im = 0; im < 4; im++) {
                int mrow = wm * 64 + im * 16 + arow_l;
                uint32_t abase = smb + so + mrow * (SA * 2) + (ks + akcol) * 2;
                ldmatrix_x4(a_h[im], abase);
                ldmatrix_x4(a_l[im], abase + A_BUF);
            }
#pragma unroll
            for (int in_ = 0; in_ < 4; in_++) {
                int ncol = wn * 32 + in_ * 8;
                uint32_t bb[4];
                uint32_t baddr = smb + so + 2 * A_BUF + bsel
                               + (ks + bkrow) * (SB * 2) + ncol * 2;
                ldmatrix_x4_trans(bb, baddr);   // bb[0..1]=Bh, bb[2..3]=Bl
#pragma unroll
                for (int im = 0; im < 4; im++) {
                    mma_bf16(acc[im][in_], a_h[im], &bb[0]);
                    mma_bf16(acc[im][in_], a_h[im], &bb[2]);
                    mma_bf16(acc[im][in_], a_l[im], &bb[0]);
                }
            }
        }
        __syncthreads();
    }

    // epilogue: bias + relu, write h1 as split bf16
    const int r_in = lane >> 2;
    const int c_in = (lane & 3) * 2;
#pragma unroll
    for (int in_ = 0; in_ < 4; in_++) {
        int col = bn + wn * 32 + in_ * 8 + c_in;
        float b0 = bias[col], b1 = bias[col + 1];
#pragma unroll
        for (int im = 0; im < 4; im++) {
            int row0 = bm + wm * 64 + im * 16 + r_in;
            if (row0 < NN) {
                float ox = fmaxf(acc[im][in_][0] + b0, 0.f);
                float oy = fmaxf(acc[im][in_][1] + b1, 0.f);
                store_split2(g_h1h, g_h1l, (size_t)row0 * HID + col, ox, oy);
            }
            int row1 = row0 + 8;
            if (row1 < NN) {
                float ox = fmaxf(acc[im][in_][2] + b0, 0.f);
                float oy = fmaxf(acc[im][in_][3] + b1, 0.f);
                store_split2(g_h1h, g_h1l, (size_t)row1 * HID + col, ox, oy);
            }
        }
    }
}

// ===================== GEMM2: h = relu(h1 @ W2 + b2) =====================
#define SB2 48
#define SA2 72
#define G2_SMEM ((HID * SB2 * 2 + 128 * SA2 * 2) * 2)

__global__ __launch_bounds__(256, 2)
void gemm2_tc(const float* __restrict__ b2) {
    extern __shared__ __align__(16) char sm2[];
    __nv_bfloat16* W2hs = reinterpret_cast<__nv_bfloat16*>(sm2);
    __nv_bfloat16* W2ls = W2hs + HID * SB2;
    __nv_bfloat16* A2h  = W2ls + HID * SB2;
    __nv_bfloat16* A2l  = A2h + 128 * SA2;

    const int tid  = threadIdx.x;
    const int lane = tid & 31;
    const int warp = tid >> 5;
    const int bm   = blockIdx.x * 128;

    for (int i = tid; i < HID * CC; i += 256) {
        int k = i / CC, n = i % CC;
        W2hs[k * SB2 + n] = g_W2h[i];
        W2ls[k * SB2 + n] = g_W2l[i];
    }

    float acc[5][4];
#pragma unroll
    for (int n = 0; n < 5; n++)
#pragma unroll
        for (int j = 0; j < 4; j++) acc[n][j] = 0.f;

    const int agrp   = lane >> 3;
    const int arow_l = (agrp & 1) * 8 + (lane & 7);
    const int akcol  = (agrp >> 1) * 8;
    const int bkrow  = lane & 15;
    const int bsel   = (lane < 16) ? 0 : HID * SB2;   // Bh vs Bl (elements)

    const int arow  = tid >> 1;
    const int apart = (tid & 1) * 32;
    const bool aok  = (bm + arow) < NN;
    const uint4 zz  = make_uint4(0, 0, 0, 0);

    for (int kc = 0; kc < 4; kc++) {
#pragma unroll
        for (int j = 0; j < 4; j++) {
            size_t gidx = (size_t)(bm + arow) * HID + kc * 64 + apart + j * 8;
            uint4 vh = aok ? *reinterpret_cast<const uint4*>(&g_h1h[gidx]) : zz;
            uint4 vl = aok ? *reinterpret_cast<const uint4*>(&g_h1l[gidx]) : zz;
            *reinterpret_cast<uint4*>(&A2h[arow * SA2 + apart + j * 8]) = vh;
            *reinterpret_cast<uint4*>(&A2l[arow * SA2 + apart + j * 8]) = vl;
        }
        __syncthreads();

#pragma unroll
        for (int ks = 0; ks < 64; ks += 16) {
            uint32_t a_h[4], a_l[4];
            ldmatrix_x4(a_h, smem_u32(&A2h[(warp * 16 + arow_l) * SA2 + ks + akcol]));
            ldmatrix_x4(a_l, smem_u32(&A2l[(warp * 16 + arow_l) * SA2 + ks + akcol]));
#pragma unroll
            for (int n = 0; n < 5; n++) {
                uint32_t bb[4];
                ldmatrix_x4_trans(bb, smem_u32(&W2hs[bsel + (kc * 64 + ks + bkrow) * SB2 + n * 8]));
                mma_bf16(acc[n], a_h, &bb[0]);
                mma_bf16(acc[n], a_h, &bb[2]);
                mma_bf16(acc[n], a_l, &bb[0]);
            }
        }
        __syncthreads();
    }

    const int r_in = lane >> 2;
    const int c_in = (lane & 3) * 2;
    const int row0 = bm + warp * 16 + r_in;
    const int row1 = row0 + 8;
#pragma unroll
    for (int n = 0; n < 5; n++) {
        int col = n * 8 + c_in;
        float bb0 = b2[col], bb1 = b2[col + 1];
        if (row0 < NN) {
            float2 o;
            o.x = fmaxf(acc[n][0] + bb0, 0.f);
            o.y = fmaxf(acc[n][1] + bb1, 0.f);
            *reinterpret_cast<float2*>(&g_h[(size_t)row0 * CC + col]) = o;
        }
        if (row1 < NN) {
            float2 o;
            o.x = fmaxf(acc[n][2] + bb0, 0.f);
            o.y = fmaxf(acc[n][3] + bb1, 0.f);
            *reinterpret_cast<float2*>(&g_h[(size_t)row1 * CC + col]) = o;
        }
    }
}

// ================= degree / CSR build =================
__global__ void zero_cnt() {
    int i = blockIdx.x * blockDim.x + threadIdx.x;
    if (i < NN) g_cnt[i] = 0;
}
__global__ void count_deg(const int* __restrict__ dst) {
    int e = blockIdx.x * blockDim.x + threadIdx.x;
    if (e < EE) atomicAdd(&g_cnt[dst[e]], 1);
}
__global__ void calc_dinv() {
    int i = blockIdx.x * blockDim.x + threadIdx.x;
    if (i < NN) g_dinv[i] = rsqrtf((float)g_cnt[i] + 1.0f);
}
__global__ void scan_rowptr() {
    __shared__ int s[1024];
    __shared__ int carry;
    const int tid = threadIdx.x;
    if (tid == 0) carry = 0;
    __syncthreads();
    for (int base = 0; base < NN; base += 1024) {
        int i = base + tid;
        int v = (i < NN) ? g_cnt[i] : 0;
        s[tid] = v;
        __syncthreads();
#pragma unroll
        for (int off = 1; off < 1024; off <<= 1) {
            int t = (tid >= off) ? s[tid - off] : 0;
            __syncthreads();
            s[tid] += t;
            __syncthreads();
        }
        if (i < NN) {
            int ex = carry + s[tid] - v;
            g_rowptr[i] = ex;
            g_cursor[i] = ex;
        }
        __syncthreads();
        if (tid == 0) carry += s[1023];
        __syncthreads();
    }
    if (tid == 0) g_rowptr[NN] = carry;
}
__global__ void fill_csr(const int* __restrict__ src, const int* __restrict__ dst) {
    int e = blockIdx.x * blockDim.x + threadIdx.x;
    if (e >= EE) return;
    int s = src[e];
    int d = dst[e];
    int pos = atomicAdd(&g_cursor[d], 1);
    g_eidx[pos] = s;
    g_ew[pos]   = g_dinv[s] * g_dinv[d];
}

// ================= fused propagation step =================
__global__ __launch_bounds__(320)
void prop_step(const float* __restrict__ z,
               float* __restrict__ zn) {
    const int tid  = blockIdx.x * blockDim.x + threadIdx.x;
    const int node = tid / 10;
    const int q    = tid % 10;
    if (node >= NN) return;

    const int beg = g_rowptr[node];
    const int end = g_rowptr[node + 1];

    const float4* __restrict__ z4 = reinterpret_cast<const float4*>(z);

    float4 acc = make_float4(0.f, 0.f, 0.f, 0.f);
#pragma unroll 2
    for (int e = beg; e < end; e++) {
        const int   s = __ldg(&g_eidx[e]);
        const float w = __ldg(&g_ew[e]);
        float4 v = __ldg(&z4[(size_t)s * 10 + q]);
        acc.x += w * v.x;
        acc.y += w * v.y;
        acc.z += w * v.z;
        acc.w += w * v.w;
    }

    const float di = g_dinv[node];
    const float sw = di * di;
    const float4 zc = z4[(size_t)node * 10 + q];
    const float4 hh = reinterpret_cast<const float4*>(g_h)[(size_t)node * 10 + q];

    float4 o;
    o.x = (1.0f - ALPHAF) * (acc.x + sw * zc.x) + ALPHAF * hh.x;
    o.y = (1.0f - ALPHAF) * (acc.y + sw * zc.y) + ALPHAF * hh.y;
    o.z = (1.0f - ALPHAF) * (acc.z + sw * zc.z) + ALPHAF * hh.z;
    o.w = (1.0f - ALPHAF) * (acc.w + sw * zc.w) + ALPHAF * hh.w;
    reinterpret_cast<float4*>(zn)[(size_t)node * 10 + q] = o;
}

// ================= launch =================
extern "C" void kernel_launch(void* const* d_in, const int* in_sizes, int n_in,
                              void* d_out, int out_size) {
    const float* x  = (const float*)d_in[0];
    const int*   ei = (const int*)  d_in[1];
    const float* W1 = (const float*)d_in[2];
    const float* b1 = (const float*)d_in[3];
    const float* W2 = (const float*)d_in[4];
    const float* b2 = (const float*)d_in[5];
    float* out = (float*)d_out;

    const int* src = ei;
    const int* dst = ei + EE;

    float *p_h, *p_z0, *p_z1;
    cudaGetSymbolAddress((void**)&p_h,  g_h);
    cudaGetSymbolAddress((void**)&p_z0, g_z0);
    cudaGetSymbolAddress((void**)&p_z1, g_z1);

    // splits
    split_x <<<(int)(((size_t)NN * FIN / 4 + 255) / 256), 256>>>(x);
    split_w1<<<(FIN * HID / 4 + 255) / 256, 256>>>(W1);
    split_w2<<<(HID * CC / 4 + 255) / 256, 256>>>(W2);

    // MLP on tensor cores
    cudaFuncSetAttribute(gemm1_tc, cudaFuncAttributeMaxDynamicSharedMemorySize, G1_SMEM);
    dim3 g1(HID / 128, (NN + 127) / 128);
    gemm1_tc<<<g1, 256, G1_SMEM>>>(b1);
    cudaFuncSetAttribute(gemm2_tc, cudaFuncAttributeMaxDynamicSharedMemorySize, G2_SMEM);
    gemm2_tc<<<(NN + 127) / 128, 256, G2_SMEM>>>(b2);

    // CSR build (by destination)
    zero_cnt <<<(NN + 255) / 256, 256>>>();
    count_deg<<<(EE + 255) / 256, 256>>>(dst);
    calc_dinv<<<(NN + 255) / 256, 256>>>();
    scan_rowptr<<<1, 1024>>>();
    fill_csr <<<(EE + 255) / 256, 256>>>(src, dst);

    // K fused propagation steps (ping-pong)
    const int threads = NN * 10;
    const int blocks  = (threads + 319) / 320;
    for (int it = 0; it < KIT; it++) {
        const float* zcur = (it == 0) ? p_h : ((it & 1) ? p_z1 : p_z0);
        float* znext = (it == KIT - 1) ? out : ((it & 1) ? p_z0 : p_z1);
        prop_step<<<blocks, 320>>>(zcur, znext);
    }
}

// round 10
// speedup vs baseline: 1.0054x; 1.0000x over previous
#include <cuda_runtime.h>
#include <cuda_bf16.h>
#include <cstdint>

#define NN   100000
#define FIN  512
#define HID  256
#define CC   40
#define EE   1600000
#define KIT  10
#define ALPHAF 0.1f

// ---- static device scratch ----
__device__ __align__(128) __nv_bfloat16 g_Xh[(size_t)NN * FIN];
__device__ __align__(128) __nv_bfloat16 g_Xl[(size_t)NN * FIN];
__device__ __align__(128) __nv_bfloat16 g_W1h[FIN * HID];   // [K][N]
__device__ __align__(128) __nv_bfloat16 g_W1l[FIN * HID];
__device__ __align__(128) __nv_bfloat16 g_h1h[(size_t)NN * HID];
__device__ __align__(128) __nv_bfloat16 g_h1l[(size_t)NN * HID];
__device__ __align__(128) __nv_bfloat16 g_W2h[HID * CC];    // [K][N]
__device__ __align__(128) __nv_bfloat16 g_W2l[HID * CC];
__device__ float g_h [NN * CC];
__device__ float g_z0[NN * CC];
__device__ float g_z1[NN * CC];
__device__ float g_dinv[NN];
__device__ int   g_cnt[NN];
__device__ int   g_rowptr[NN + 1];
__device__ int   g_cursor[NN];
__device__ int   g_eidx[EE];
__device__ float g_ew  [EE];

// ===================== helpers =====================
__device__ __forceinline__ uint32_t smem_u32(const void* p) {
    return (uint32_t)__cvta_generic_to_shared(p);
}
__device__ __forceinline__ void ldmatrix_x4(uint32_t* r, uint32_t addr) {
    asm volatile("ldmatrix.sync.aligned.m8n8.x4.shared.b16 {%0,%1,%2,%3}, [%4];"
                 : "=r"(r[0]), "=r"(r[1]), "=r"(r[2]), "=r"(r[3]) : "r"(addr));
}
__device__ __forceinline__ void ldmatrix_x4_trans(uint32_t* r, uint32_t addr) {
    asm volatile("ldmatrix.sync.aligned.m8n8.x4.trans.shared.b16 {%0,%1,%2,%3}, [%4];"
                 : "=r"(r[0]), "=r"(r[1]), "=r"(r[2]), "=r"(r[3]) : "r"(addr));
}
__device__ __forceinline__ void mma_bf16(float* c, const uint32_t* a, const uint32_t* b) {
    asm volatile("mma.sync.aligned.m16n8k16.row.col.f32.bf16.bf16.f32 "
                 "{%0,%1,%2,%3}, {%4,%5,%6,%7}, {%8,%9}, {%0,%1,%2,%3};"
                 : "+f"(c[0]), "+f"(c[1]), "+f"(c[2]), "+f"(c[3])
                 : "r"(a[0]), "r"(a[1]), "r"(a[2]), "r"(a[3]), "r"(b[0]), "r"(b[1]));
}
__device__ __forceinline__ void cp16z(uint32_t dst, const void* src, uint32_t sz) {
    asm volatile("cp.async.cg.shared.global [%0], [%1], 16, %2;"
                 :: "r"(dst), "l"(src), "r"(sz));
}
__device__ __forceinline__ void cp_commit() {
    asm volatile("cp.async.commit_group;");
}
// truncation split: f = hi(bf16 trunc) + lo(bf16 rn)
__device__ __forceinline__ void split4(float4 v, uint2& hi, uint2& lo) {
    uint32_t b0 = __float_as_uint(v.x), b1 = __float_as_uint(v.y);
    uint32_t b2 = __float_as_uint(v.z), b3 = __float_as_uint(v.w);
    float h0 = __uint_as_float(b0 & 0xFFFF0000u);
    float h1 = __uint_as_float(b1 & 0xFFFF0000u);
    float h2 = __uint_as_float(b2 & 0xFFFF0000u);
    float h3 = __uint_as_float(b3 & 0xFFFF0000u);
    hi.x = __byte_perm(b0, b1, 0x7632);
    hi.y = __byte_perm(b2, b3, 0x7632);
    __nv_bfloat162 p0 = __floats2bfloat162_rn(v.x - h0, v.y - h1);
    __nv_bfloat162 p1 = __floats2bfloat162_rn(v.z - h2, v.w - h3);
    lo.x = *reinterpret_cast<uint32_t*>(&p0);
    lo.y = *reinterpret_cast<uint32_t*>(&p1);
}
__device__ __forceinline__ void store_split2(__nv_bfloat16* hibuf, __nv_bfloat16* lobuf,
                                             size_t idx, float x, float y) {
    uint32_t bx = __float_as_uint(x), by = __float_as_uint(y);
    float hx = __uint_as_float(bx & 0xFFFF0000u);
    float hy = __uint_as_float(by & 0xFFFF0000u);
    reinterpret_cast<uint32_t*>(hibuf)[idx >> 1] = __byte_perm(bx, by, 0x7632);
    __nv_bfloat162 lo = __floats2bfloat162_rn(x - hx, y - hy);
    reinterpret_cast<uint32_t*>(lobuf)[idx >> 1] = *reinterpret_cast<uint32_t*>(&lo);
}

// ===================== one-off split kernels =====================
__global__ void split_x(const float* __restrict__ X) {
    size_t i = (size_t)blockIdx.x * blockDim.x + threadIdx.x;
    if (i >= (size_t)NN * FIN / 4) return;
    float4 v = reinterpret_cast<const float4*>(X)[i];
    uint2 hi, lo;
    split4(v, hi, lo);
    reinterpret_cast<uint2*>(g_Xh)[i] = hi;
    reinterpret_cast<uint2*>(g_Xl)[i] = lo;
}
__global__ void split_w1(const float* __restrict__ W1) {
    int i = blockIdx.x * blockDim.x + threadIdx.x;
    if (i >= FIN * HID / 4) return;
    float4 v = reinterpret_cast<const float4*>(W1)[i];
    uint2 hi, lo;
    split4(v, hi, lo);
    reinterpret_cast<uint2*>(g_W1h)[i] = hi;
    reinterpret_cast<uint2*>(g_W1l)[i] = lo;
}
__global__ void split_w2(const float* __restrict__ W2) {
    int i = blockIdx.x * blockDim.x + threadIdx.x;
    if (i >= HID * CC / 4) return;
    float4 v = reinterpret_cast<const float4*>(W2)[i];
    uint2 hi, lo;
    split4(v, hi, lo);
    reinterpret_cast<uint2*>(g_W2h)[i] = hi;
    reinterpret_cast<uint2*>(g_W2l)[i] = lo;
}

// ===================== GEMM1: h1 = relu(X @ W1 + b1) =====================
// double-buffered cp.async, 2 CTAs/SM, merged hi/lo B ldmatrix
#define SA 40
#define SB 136
#define A_BUF (128 * SA * 2)          // 10240 B
#define B_BUF (32 * SB * 2)           // 8704 B
#define ST1   (2 * A_BUF + 2 * B_BUF) // 37888 B per stage
#define G1_SMEM (2 * ST1)             // 75776 B
#define NKT (FIN / 32)                // 16

__global__ __launch_bounds__(256, 2)
void gemm1_tc(const float* __restrict__ bias) {
    extern __shared__ __align__(16) char sm1[];

    const int tid  = threadIdx.x;
    const int lane = tid & 31;
    const int warp = tid >> 5;
    const int wm   = warp >> 2;
    const int wn   = warp & 3;
    const int bm   = blockIdx.y * 128;
    const int bn   = blockIdx.x * 128;

    // cp.async mapping
    const int arow = tid >> 1;
    const int akp  = (tid & 1) * 16;
    const int brow = tid >> 3;
    const int bcol = (tid & 7) * 16;
    const uint32_t xsz = ((bm + arow) < NN) ? 16u : 0u;

    const __nv_bfloat16* srcAh = g_Xh + (size_t)(bm + arow) * FIN + akp;
    const __nv_bfloat16* srcAl = g_Xl + (size_t)(bm + arow) * FIN + akp;
    const __nv_bfloat16* srcBh = g_W1h + (size_t)brow * HID + bn + bcol;
    const __nv_bfloat16* srcBl = g_W1l + (size_t)brow * HID + bn + bcol;

    const uint32_t smb = smem_u32(sm1);
    const uint32_t dAh = smb + arow * (SA * 2) + akp * 2;
    const uint32_t dAl = dAh + A_BUF;
    const uint32_t dBh = smb + 2 * A_BUF + brow * (SB * 2) + bcol * 2;
    const uint32_t dBl = dBh + B_BUF;

    auto load_stage = [&](int kt, int s) {
        const uint32_t so = (uint32_t)s * ST1;
        const int ko = kt * 32;
        cp16z(dAh + so,      srcAh + ko,     xsz);
        cp16z(dAh + so + 16, srcAh + ko + 8, xsz);
        cp16z(dAl + so,      srcAl + ko,     xsz);
        cp16z(dAl + so + 16, srcAl + ko + 8, xsz);
        cp16z(dBh + so,      srcBh + (size_t)ko * HID,     16u);
        cp16z(dBh + so + 16, srcBh + (size_t)ko * HID + 8, 16u);
        cp16z(dBl + so,      srcBl + (size_t)ko * HID,     16u);
        cp16z(dBl + so + 16, srcBl + (size_t)ko * HID + 8, 16u);
        cp_commit();
    };

    float acc[4][4][4];
#pragma unroll
    for (int i = 0; i < 4; i++)
#pragma unroll
        for (int j = 0; j < 4; j++)
#pragma unroll
            for (int k = 0; k < 4; k++) acc[i][j][k] = 0.f;

    const int agrp   = lane >> 3;
    const int arow_l = (agrp & 1) * 8 + (lane & 7);
    const int akcol  = (agrp >> 1) * 8;
    // merged-B ldmatrix: lanes 0-15 read Bh rows, lanes 16-31 read Bl rows
    const int bkrow  = lane & 15;
    const uint32_t bsel = (lane < 16) ? 0u : (uint32_t)B_BUF;

    load_stage(0, 0);

    for (int kt = 0; kt < NKT; kt++) {
        const int s = kt & 1;
        const uint32_t so = (uint32_t)s * ST1;

        if (kt + 1 < NKT) {
            load_stage(kt + 1, s ^ 1);
            asm volatile("cp.async.wait_group 1;");
        } else {
            asm volatile("cp.async.wait_group 0;");
        }
        __syncthreads();

#pragma unroll
        for (int ks = 0; ks < 32; ks += 16) {
            uint32_t a_h[4][4], a_l[4][4];
#pragma unroll
            for (int im = 0; im < 4; im++) {
                int mrow = wm * 64 + im * 16 + arow_l;
                uint32_t abase = smb + so + mrow * (SA * 2) + (ks + akcol) * 2;
                ldmatrix_x4(a_h[im], abase);
                ldmatrix_x4(a_l[im], abase + A_BUF);
            }
#pragma unroll
            for (int in_ = 0; in_ < 4; in_++) {
                int ncol = wn * 32 + in_ * 8;
                uint32_t bb[4];
                uint32_t baddr = smb + so + 2 * A_BUF + bsel
                               + (ks + bkrow) * (SB * 2) + ncol * 2;
                ldmatrix_x4_trans(bb, baddr);   // bb[0..1]=Bh, bb[2..3]=Bl
#pragma unroll
                for (int im = 0; im < 4; im++) {
                    mma_bf16(acc[im][in_], a_h[im], &bb[0]);
                    mma_bf16(acc[im][in_], a_h[im], &bb[2]);
                    mma_bf16(acc[im][in_], a_l[im], &bb[0]);
                }
            }
        }
        __syncthreads();
    }

    // epilogue: bias + relu, write h1 as split bf16
    const int r_in = lane >> 2;
    const int c_in = (lane & 3) * 2;
#pragma unroll
    for (int in_ = 0; in_ < 4; in_++) {
        int col = bn + wn * 32 + in_ * 8 + c_in;
        float b0 = bias[col], b1 = bias[col + 1];
#pragma unroll
        for (int im = 0; im < 4; im++) {
            int row0 = bm + wm * 64 + im * 16 + r_in;
            if (row0 < NN) {
                float ox = fmaxf(acc[im][in_][0] + b0, 0.f);
                float oy = fmaxf(acc[im][in_][1] + b1, 0.f);
                store_split2(g_h1h, g_h1l, (size_t)row0 * HID + col, ox, oy);
            }
            int row1 = row0 + 8;
            if (row1 < NN) {
                float ox = fmaxf(acc[im][in_][2] + b0, 0.f);
                float oy = fmaxf(acc[im][in_][3] + b1, 0.f);
                store_split2(g_h1h, g_h1l, (size_t)row1 * HID + col, ox, oy);
            }
        }
    }
}

// ===================== GEMM2: h = relu(h1 @ W2 + b2) =====================
#define SB2 48
#define SA2 72
#define G2_SMEM ((HID * SB2 * 2 + 128 * SA2 * 2) * 2)

__global__ __launch_bounds__(256, 2)
void gemm2_tc(const float* __restrict__ b2) {
    extern __shared__ __align__(16) char sm2[];
    __nv_bfloat16* W2hs = reinterpret_cast<__nv_bfloat16*>(sm2);
    __nv_bfloat16* W2ls = W2hs + HID * SB2;
    __nv_bfloat16* A2h  = W2ls + HID * SB2;
    __nv_bfloat16* A2l  = A2h + 128 * SA2;

    const int tid  = threadIdx.x;
    const int lane = tid & 31;
    const int warp = tid >> 5;
    const int bm   = blockIdx.x * 128;

    for (int i = tid; i < HID * CC; i += 256) {
        int k = i / CC, n = i % CC;
        W2hs[k * SB2 + n] = g_W2h[i];
        W2ls[k * SB2 + n] = g_W2l[i];
    }

    float acc[5][4];
#pragma unroll
    for (int n = 0; n < 5; n++)
#pragma unroll
        for (int j = 0; j < 4; j++) acc[n][j] = 0.f;

    const int agrp   = lane >> 3;
    const int arow_l = (agrp & 1) * 8 + (lane & 7);
    const int akcol  = (agrp >> 1) * 8;
    const int bkrow  = lane & 15;
    const int bsel   = (lane < 16) ? 0 : HID * SB2;   // Bh vs Bl (elements)

    const int arow  = tid >> 1;
    const int apart = (tid & 1) * 32;
    const bool aok  = (bm + arow) < NN;
    const uint4 zz  = make_uint4(0, 0, 0, 0);

    for (int kc = 0; kc < 4; kc++) {
#pragma unroll
        for (int j = 0; j < 4; j++) {
            size_t gidx = (size_t)(bm + arow) * HID + kc * 64 + apart + j * 8;
            uint4 vh = aok ? *reinterpret_cast<const uint4*>(&g_h1h[gidx]) : zz;
            uint4 vl = aok ? *reinterpret_cast<const uint4*>(&g_h1l[gidx]) : zz;
            *reinterpret_cast<uint4*>(&A2h[arow * SA2 + apart + j * 8]) = vh;
            *reinterpret_cast<uint4*>(&A2l[arow * SA2 + apart + j * 8]) = vl;
        }
        __syncthreads();

#pragma unroll
        for (int ks = 0; ks < 64; ks += 16) {
            uint32_t a_h[4], a_l[4];
            ldmatrix_x4(a_h, smem_u32(&A2h[(warp * 16 + arow_l) * SA2 + ks + akcol]));
            ldmatrix_x4(a_l, smem_u32(&A2l[(warp * 16 + arow_l) * SA2 + ks + akcol]));
#pragma unroll
            for (int n = 0; n < 5; n++) {
                uint32_t bb[4];
                ldmatrix_x4_trans(bb, smem_u32(&W2hs[bsel + (kc * 64 + ks + bkrow) * SB2 + n * 8]));
                mma_bf16(acc[n], a_h, &bb[0]);
                mma_bf16(acc[n], a_h, &bb[2]);
                mma_bf16(acc[n], a_l, &bb[0]);
            }
        }
        __syncthreads();
    }

    const int r_in = lane >> 2;
    const int c_in = (lane & 3) * 2;
    const int row0 = bm + warp * 16 + r_in;
    const int row1 = row0 + 8;
#pragma unroll
    for (int n = 0; n < 5; n++) {
        int col = n * 8 + c_in;
        float bb0 = b2[col], bb1 = b2[col + 1];
        if (row0 < NN) {
            float2 o;
            o.x = fmaxf(acc[n][0] + bb0, 0.f);
            o.y = fmaxf(acc[n][1] + bb1, 0.f);
            *reinterpret_cast<float2*>(&g_h[(size_t)row0 * CC + col]) = o;
        }
        if (row1 < NN) {
            float2 o;
            o.x = fmaxf(acc[n][2] + bb0, 0.f);
            o.y = fmaxf(acc[n][3] + bb1, 0.f);
            *reinterpret_cast<float2*>(&g_h[(size_t)row1 * CC + col]) = o;
        }
    }
}

// ================= degree / CSR build =================
__global__ void zero_cnt() {
    int i = blockIdx.x * blockDim.x + threadIdx.x;
    if (i < NN) g_cnt[i] = 0;
}
__global__ void count_deg(const int* __restrict__ dst) {
    int e = blockIdx.x * blockDim.x + threadIdx.x;
    if (e < EE) atomicAdd(&g_cnt[dst[e]], 1);
}
__global__ void calc_dinv() {
    int i = blockIdx.x * blockDim.x + threadIdx.x;
    if (i < NN) g_dinv[i] = rsqrtf((float)g_cnt[i] + 1.0f);
}
__global__ void scan_rowptr() {
    __shared__ int s[1024];
    __shared__ int carry;
    const int tid = threadIdx.x;
    if (tid == 0) carry = 0;
    __syncthreads();
    for (int base = 0; base < NN; base += 1024) {
        int i = base + tid;
        int v = (i < NN) ? g_cnt[i] : 0;
        s[tid] = v;
        __syncthreads();
#pragma unroll
        for (int off = 1; off < 1024; off <<= 1) {
            int t = (tid >= off) ? s[tid - off] : 0;
            __syncthreads();
            s[tid] += t;
            __syncthreads();
        }
        if (i < NN) {
            int ex = carry + s[tid] - v;
            g_rowptr[i] = ex;
            g_cursor[i] = ex;
        }
        __syncthreads();
        if (tid == 0) carry += s[1023];
        __syncthreads();
    }
    if (tid == 0) g_rowptr[NN] = carry;
}
__global__ void fill_csr(const int* __restrict__ src, const int* __restrict__ dst) {
    int e = blockIdx.x * blockDim.x + threadIdx.x;
    if (e >= EE) return;
    int s = src[e];
    int d = dst[e];
    int pos = atomicAdd(&g_cursor[d], 1);
    g_eidx[pos] = s;
    g_ew[pos]   = g_dinv[s] * g_dinv[d];
}

// ================= fused propagation step =================
__global__ __launch_bounds__(320)
void prop_step(const float* __restrict__ z,
               float* __restrict__ zn) {
    const int tid  = blockIdx.x * blockDim.x + threadIdx.x;
    const int node = tid / 10;
    const int q    = tid % 10;
    if (node >= NN) return;

    const int beg = g_rowptr[node];
    const int end = g_rowptr[node + 1];

    const float4* __restrict__ z4 = reinterpret_cast<const float4*>(z);

    float4 acc = make_float4(0.f, 0.f, 0.f, 0.f);
#pragma unroll 2
    for (int e = beg; e < end; e++) {
        const int   s = __ldg(&g_eidx[e]);
        const float w = __ldg(&g_ew[e]);
        float4 v = __ldg(&z4[(size_t)s * 10 + q]);
        acc.x += w * v.x;
        acc.y += w * v.y;
        acc.z += w * v.z;
        acc.w += w * v.w;
    }

    const float di = g_dinv[node];
    const float sw = di * di;
    const float4 zc = z4[(size_t)node * 10 + q];
    const float4 hh = reinterpret_cast<const float4*>(g_h)[(size_t)node * 10 + q];

    float4 o;
    o.x = (1.0f - ALPHAF) * (acc.x + sw * zc.x) + ALPHAF * hh.x;
    o.y = (1.0f - ALPHAF) * (acc.y + sw * zc.y) + ALPHAF * hh.y;
    o.z = (1.0f - ALPHAF) * (acc.z + sw * zc.z) + ALPHAF * hh.z;
    o.w = (1.0f - ALPHAF) * (acc.w + sw * zc.w) + ALPHAF * hh.w;
    reinterpret_cast<float4*>(zn)[(size_t)node * 10 + q] = o;
}

// ================= launch =================
extern "C" void kernel_launch(void* const* d_in, const int* in_sizes, int n_in,
                              void* d_out, int out_size) {
    const float* x  = (const float*)d_in[0];
    const int*   ei = (const int*)  d_in[1];
    const float* W1 = (const float*)d_in[2];
    const float* b1 = (const float*)d_in[3];
    const float* W2 = (const float*)d_in[4];
    const float* b2 = (const float*)d_in[5];
    float* out = (float*)d_out;

    const int* src = ei;
    const int* dst = ei + EE;

    float *p_h, *p_z0, *p_z1;
    cudaGetSymbolAddress((void**)&p_h,  g_h);
    cudaGetSymbolAddress((void**)&p_z0, g_z0);
    cudaGetSymbolAddress((void**)&p_z1, g_z1);

    // splits
    split_x <<<(int)(((size_t)NN * FIN / 4 + 255) / 256), 256>>>(x);
    split_w1<<<(FIN * HID / 4 + 255) / 256, 256>>>(W1);
    split_w2<<<(HID * CC / 4 + 255) / 256, 256>>>(W2);

    // MLP on tensor cores
    cudaFuncSetAttribute(gemm1_tc, cudaFuncAttributeMaxDynamicSharedMemorySize, G1_SMEM);
    dim3 g1(HID / 128, (NN + 127) / 128);
    gemm1_tc<<<g1, 256, G1_SMEM>>>(b1);
    cudaFuncSetAttribute(gemm2_tc, cudaFuncAttributeMaxDynamicSharedMemorySize, G2_SMEM);
    gemm2_tc<<<(NN + 127) / 128, 256, G2_SMEM>>>(b2);

    // CSR build (by destination)
    zero_cnt <<<(NN + 255) / 256, 256>>>();
    count_deg<<<(EE + 255) / 256, 256>>>(dst);
    calc_dinv<<<(NN + 255) / 256, 256>>>();
    scan_rowptr<<<1, 1024>>>();
    fill_csr <<<(EE + 255) / 256, 256>>>(src, dst);

    // K fused propagation steps (ping-pong)
    const int threads = NN * 10;
    const int blocks  = (threads + 319) / 320;
    for (int it = 0; it < KIT; it++) {
        const float* zcur = (it == 0) ? p_h : ((it & 1) ? p_z1 : p_z0);
        float* znext = (it == KIT - 1) ? out : ((it & 1) ? p_z0 : p_z1);
        prop_step<<<blocks, 320>>>(zcur, znext);
    }
}